// round 3
// baseline (speedup 1.0000x reference)
#include <cuda_runtime.h>
#include <cuda_bf16.h>
#include <math.h>

// Problem constants (shapes fixed by setup_inputs; B derived at launch)
#define MAXB 4096
#define NEXP 8
#define DIN 768
#define DH 2048
#define DOUT 768
#define KSEL 2

typedef unsigned long long ull;

// ---------------- scratch (device globals; no allocation allowed) ------------
__device__ int   g_counts[NEXP];
__device__ int   g_offsets[NEXP];
__device__ int   g_cursor[NEXP];
__device__ float g_importance[NEXP];
__device__ int   g_tok_e[MAXB * KSEL];       // top-2 expert ids per token
__device__ float g_tok_g[MAXB * KSEL];       // top-2 gate weights per token
__device__ int   g_assign_tok[MAXB * KSEL];  // compacted per-expert token lists
__device__ int   g_assign_slot[MAXB * KSEL]; // token,j -> slot in compact list
__device__ float g_hbuf[(size_t)MAXB * KSEL * DH];    // 64 MB
__device__ float g_zbuf[(size_t)MAXB * KSEL * DOUT];  // 24 MB

// ---------------- helpers ----------------------------------------------------
__device__ __forceinline__ float gelu_tanh(float v) {
    // JAX default gelu (approximate=True)
    float v3 = v * v * v;
    return 0.5f * v * (1.0f + tanhf(0.7978845608028654f * (v + 0.044715f * v3)));
}

// packed fp32x2 FMA (sm_100+): d = a*b + d  — 2x fp32 work per issue slot
__device__ __forceinline__ void ffma2(ull& d, ull a, ull b) {
    asm volatile("fma.rn.f32x2 %0, %1, %2, %0;" : "+l"(d) : "l"(a), "l"(b));
}
__device__ __forceinline__ ull pack2(float v) {
    ull r;
    asm("mov.b64 %0, {%1, %1};" : "=l"(r) : "r"(__float_as_uint(v)));
    return r;
}
__device__ __forceinline__ float2 unpack2(ull v) {
    unsigned lo, hi;
    asm("mov.b64 {%0, %1}, %2;" : "=r"(lo), "=r"(hi) : "l"(v));
    return make_float2(__uint_as_float(lo), __uint_as_float(hi));
}

// ---------------- kernel 0: zero per-launch state ----------------------------
__global__ void init_kernel() {
    int t = threadIdx.x;
    if (t < NEXP) {
        g_counts[t] = 0;
        g_importance[t] = 0.0f;
    }
}

// ---------------- kernel 1: gating (one warp per token) ----------------------
__global__ void gating_kernel(const float* __restrict__ x,
                              const float* __restrict__ wg, int B) {
    __shared__ float sW[NEXP][DIN];  // transposed for conflict-free reads
    for (int i = threadIdx.x; i < NEXP * DIN; i += blockDim.x) {
        int e = i / DIN, c = i % DIN;
        sW[e][c] = wg[c * NEXP + e];
    }
    __syncthreads();

    int warp = (blockIdx.x * blockDim.x + threadIdx.x) >> 5;
    int lane = threadIdx.x & 31;
    if (warp >= B) return;

    const float* xr = x + (size_t)warp * DIN;
    float acc[NEXP];
#pragma unroll
    for (int e = 0; e < NEXP; e++) acc[e] = 0.0f;

    for (int i = lane; i < DIN; i += 32) {
        float xv = xr[i];
#pragma unroll
        for (int e = 0; e < NEXP; e++) acc[e] += xv * sW[e][i];
    }
#pragma unroll
    for (int off = 16; off; off >>= 1) {
#pragma unroll
        for (int e = 0; e < NEXP; e++)
            acc[e] += __shfl_down_sync(0xffffffffu, acc[e], off);
    }

    if (lane == 0) {
        // top-1 (strict > keeps earliest index, matching lax.top_k tie rule)
        int i1 = 0; float v1 = acc[0];
#pragma unroll
        for (int e = 1; e < NEXP; e++)
            if (acc[e] > v1) { v1 = acc[e]; i1 = e; }
        // top-2
        int i2 = -1; float v2 = -INFINITY;
#pragma unroll
        for (int e = 0; e < NEXP; e++)
            if (e != i1 && acc[e] > v2) { v2 = acc[e]; i2 = e; }

        // softmax over the two kept logits (v1 >= v2, stable)
        float e2 = expf(v2 - v1);
        float inv = 1.0f / (1.0f + e2);
        float gA = inv;
        float gB = e2 * inv;

        g_tok_e[2 * warp + 0] = i1;
        g_tok_e[2 * warp + 1] = i2;
        g_tok_g[2 * warp + 0] = gA;
        g_tok_g[2 * warp + 1] = gB;
        atomicAdd(&g_counts[i1], 1);
        atomicAdd(&g_counts[i2], 1);
        atomicAdd(&g_importance[i1], gA);
        atomicAdd(&g_importance[i2], gB);
    }
}

// ---------------- kernel 2: prefix sums + aux loss ---------------------------
__global__ void prefix_loss_kernel(float* __restrict__ d_out, int B, int out_size) {
    if (threadIdx.x == 0 && blockIdx.x == 0) {
        int off = 0;
        for (int e = 0; e < NEXP; e++) {
            g_offsets[e] = off;
            g_cursor[e] = off;
            off += g_counts[e];
        }
        // cv_squared(importance) + cv_squared(load), var ddof=1
        float mi = 0.0f, ml = 0.0f;
        for (int e = 0; e < NEXP; e++) { mi += g_importance[e]; ml += (float)g_counts[e]; }
        mi /= NEXP; ml /= NEXP;
        float vi = 0.0f, vl = 0.0f;
        for (int e = 0; e < NEXP; e++) {
            float d1 = g_importance[e] - mi; vi += d1 * d1;
            float d2 = (float)g_counts[e] - ml; vl += d2 * d2;
        }
        vi /= (NEXP - 1); vl /= (NEXP - 1);
        float loss = 0.01f * (vi / (mi * mi + 1e-10f) + vl / (ml * ml + 1e-10f));
        if (out_size > B * DOUT) d_out[(size_t)B * DOUT] = loss;
    }
}

// ---------------- kernel 3: scatter token -> compact per-expert lists --------
__global__ void scatter_kernel(int B) {
    int b = blockIdx.x * blockDim.x + threadIdx.x;
    if (b >= B) return;
#pragma unroll
    for (int j = 0; j < KSEL; j++) {
        int e = g_tok_e[2 * b + j];
        int slot = atomicAdd(&g_cursor[e], 1);
        g_assign_tok[slot] = b;
        g_assign_slot[2 * b + j] = slot;
    }
}

// ============================================================================
// Grouped GEMM core: 64(M) x 128(N) x 32(K) tile, 256 threads, 4x8 per-thread
// micro-tile held as 16 packed f32x2 accumulators (fma.rn.f32x2).
// Register double-buffering: next tile's GMEM loads issue before compute.
// Thread map (compute): tx = tid&15 (N cols tx*4.. and 64+tx*4..), ty = tid>>4.
// Thread map (A load):  rows am, am+32 (am = tid>>3), k-cols ak..ak+3.
// Thread map (B load):  rows bk+8t (bk = tid>>5, t=0..3), cols bn..bn+3.
// ============================================================================

// ---------------- kernel 4: grouped GEMM1 + GELU -----------------------------
// h[slot, :] = gelu(x[tok, :] @ W1[e] + b1[e])
__global__ __launch_bounds__(256) void gemm1_kernel(const float* __restrict__ x,
                                                    const float* __restrict__ W1,
                                                    const float* __restrict__ b1) {
    const int e = blockIdx.z;
    const int cnt = g_counts[e];
    const int m0 = blockIdx.y * 64;
    if (m0 >= cnt) return;
    const int n0 = blockIdx.x * 128;
    const int seg = g_offsets[e];

    __shared__ __align__(16) float As[32][64];
    __shared__ __align__(16) float Bs[32][128];
    __shared__ int toks[64];

    const int tid = threadIdx.x;
    if (tid < 64) {
        int m = m0 + tid;
        toks[tid] = (m < cnt) ? g_assign_tok[seg + m] : -1;
    }
    __syncthreads();

    const int tx = tid & 15, ty = tid >> 4;
    const int am = tid >> 3, ak = (tid & 7) * 4;   // A: rows am, am+32
    const int bk = tid >> 5, bn = (tid & 31) * 4;  // B: rows bk+8t
    const int tokA0 = toks[am];
    const int tokA1 = toks[am + 32];
    const float* W = W1 + (size_t)e * DIN * DH;

    ull c[4][4];
#pragma unroll
    for (int i = 0; i < 4; i++)
#pragma unroll
        for (int j = 0; j < 4; j++) c[i][j] = 0ULL;

    float4 pa0, pa1, pb[4];
    // initial prefetch (k0 = 0)
    pa0 = (tokA0 >= 0) ? *(const float4*)(x + (size_t)tokA0 * DIN + ak)
                       : make_float4(0.f, 0.f, 0.f, 0.f);
    pa1 = (tokA1 >= 0) ? *(const float4*)(x + (size_t)tokA1 * DIN + ak)
                       : make_float4(0.f, 0.f, 0.f, 0.f);
#pragma unroll
    for (int t = 0; t < 4; t++)
        pb[t] = *(const float4*)(W + (size_t)(bk + 8 * t) * DH + n0 + bn);

    for (int k0 = 0; k0 < DIN; k0 += 32) {
        // stage current tile into smem
        As[ak + 0][am] = pa0.x; As[ak + 1][am] = pa0.y;
        As[ak + 2][am] = pa0.z; As[ak + 3][am] = pa0.w;
        As[ak + 0][am + 32] = pa1.x; As[ak + 1][am + 32] = pa1.y;
        As[ak + 2][am + 32] = pa1.z; As[ak + 3][am + 32] = pa1.w;
#pragma unroll
        for (int t = 0; t < 4; t++)
            *(float4*)&Bs[bk + 8 * t][bn] = pb[t];
        __syncthreads();

        // prefetch next tile (overlaps with compute below)
        const int kn = k0 + 32;
        if (kn < DIN) {
            pa0 = (tokA0 >= 0) ? *(const float4*)(x + (size_t)tokA0 * DIN + kn + ak)
                               : make_float4(0.f, 0.f, 0.f, 0.f);
            pa1 = (tokA1 >= 0) ? *(const float4*)(x + (size_t)tokA1 * DIN + kn + ak)
                               : make_float4(0.f, 0.f, 0.f, 0.f);
#pragma unroll
            for (int t = 0; t < 4; t++)
                pb[t] = *(const float4*)(W + (size_t)(kn + bk + 8 * t) * DH + n0 + bn);
        }

#pragma unroll
        for (int k = 0; k < 32; k++) {
            float4 a4 = *(const float4*)&As[k][ty * 4];
            ulonglong2 b0 = *(const ulonglong2*)&Bs[k][tx * 4];
            ulonglong2 b1v = *(const ulonglong2*)&Bs[k][64 + tx * 4];
            ull ap0 = pack2(a4.x), ap1 = pack2(a4.y);
            ull ap2 = pack2(a4.z), ap3 = pack2(a4.w);
            ffma2(c[0][0], ap0, b0.x); ffma2(c[0][1], ap0, b0.y);
            ffma2(c[0][2], ap0, b1v.x); ffma2(c[0][3], ap0, b1v.y);
            ffma2(c[1][0], ap1, b0.x); ffma2(c[1][1], ap1, b0.y);
            ffma2(c[1][2], ap1, b1v.x); ffma2(c[1][3], ap1, b1v.y);
            ffma2(c[2][0], ap2, b0.x); ffma2(c[2][1], ap2, b0.y);
            ffma2(c[2][2], ap2, b1v.x); ffma2(c[2][3], ap2, b1v.y);
            ffma2(c[3][0], ap3, b0.x); ffma2(c[3][1], ap3, b0.y);
            ffma2(c[3][2], ap3, b1v.x); ffma2(c[3][3], ap3, b1v.y);
        }
        __syncthreads();
    }

#pragma unroll
    for (int i = 0; i < 4; i++) {
        int m = m0 + ty * 4 + i;
        if (m >= cnt) break;
        float* hrow = g_hbuf + (size_t)(seg + m) * DH;
#pragma unroll
        for (int j = 0; j < 4; j++) {
            int col = n0 + ((j >> 1) ? 64 : 0) + tx * 4 + (j & 1) * 2;
            float2 p = unpack2(c[i][j]);
            hrow[col + 0] = gelu_tanh(p.x + b1[e * DH + col + 0]);
            hrow[col + 1] = gelu_tanh(p.y + b1[e * DH + col + 1]);
        }
    }
}

// ---------------- kernel 5: grouped GEMM2 ------------------------------------
// z[slot, :] = h[slot, :] @ W2[e] + b2[e]
__global__ __launch_bounds__(256) void gemm2_kernel(const float* __restrict__ W2,
                                                    const float* __restrict__ b2) {
    const int e = blockIdx.z;
    const int cnt = g_counts[e];
    const int m0 = blockIdx.y * 64;
    if (m0 >= cnt) return;
    const int n0 = blockIdx.x * 128;
    const int seg = g_offsets[e];

    __shared__ __align__(16) float As[32][64];
    __shared__ __align__(16) float Bs[32][128];

    const int tid = threadIdx.x;
    const int tx = tid & 15, ty = tid >> 4;
    const int am = tid >> 3, ak = (tid & 7) * 4;
    const int bk = tid >> 5, bn = (tid & 31) * 4;
    const bool ok0 = (m0 + am) < cnt;
    const bool ok1 = (m0 + am + 32) < cnt;
    const float* arow0 = g_hbuf + (size_t)(seg + m0 + am) * DH;
    const float* arow1 = g_hbuf + (size_t)(seg + m0 + am + 32) * DH;
    const float* W = W2 + (size_t)e * DH * DOUT;

    ull c[4][4];
#pragma unroll
    for (int i = 0; i < 4; i++)
#pragma unroll
        for (int j = 0; j < 4; j++) c[i][j] = 0ULL;

    float4 pa0, pa1, pb[4];
    pa0 = ok0 ? *(const float4*)(arow0 + ak) : make_float4(0.f, 0.f, 0.f, 0.f);
    pa1 = ok1 ? *(const float4*)(arow1 + ak) : make_float4(0.f, 0.f, 0.f, 0.f);
#pragma unroll
    for (int t = 0; t < 4; t++)
        pb[t] = *(const float4*)(W + (size_t)(bk + 8 * t) * DOUT + n0 + bn);

    for (int k0 = 0; k0 < DH; k0 += 32) {
        As[ak + 0][am] = pa0.x; As[ak + 1][am] = pa0.y;
        As[ak + 2][am] = pa0.z; As[ak + 3][am] = pa0.w;
        As[ak + 0][am + 32] = pa1.x; As[ak + 1][am + 32] = pa1.y;
        As[ak + 2][am + 32] = pa1.z; As[ak + 3][am + 32] = pa1.w;
#pragma unroll
        for (int t = 0; t < 4; t++)
            *(float4*)&Bs[bk + 8 * t][bn] = pb[t];
        __syncthreads();

        const int kn = k0 + 32;
        if (kn < DH) {
            pa0 = ok0 ? *(const float4*)(arow0 + kn + ak) : make_float4(0.f, 0.f, 0.f, 0.f);
            pa1 = ok1 ? *(const float4*)(arow1 + kn + ak) : make_float4(0.f, 0.f, 0.f, 0.f);
#pragma unroll
            for (int t = 0; t < 4; t++)
                pb[t] = *(const float4*)(W + (size_t)(kn + bk + 8 * t) * DOUT + n0 + bn);
        }

#pragma unroll
        for (int k = 0; k < 32; k++) {
            float4 a4 = *(const float4*)&As[k][ty * 4];
            ulonglong2 b0 = *(const ulonglong2*)&Bs[k][tx * 4];
            ulonglong2 b1v = *(const ulonglong2*)&Bs[k][64 + tx * 4];
            ull ap0 = pack2(a4.x), ap1 = pack2(a4.y);
            ull ap2 = pack2(a4.z), ap3 = pack2(a4.w);
            ffma2(c[0][0], ap0, b0.x); ffma2(c[0][1], ap0, b0.y);
            ffma2(c[0][2], ap0, b1v.x); ffma2(c[0][3], ap0, b1v.y);
            ffma2(c[1][0], ap1, b0.x); ffma2(c[1][1], ap1, b0.y);
            ffma2(c[1][2], ap1, b1v.x); ffma2(c[1][3], ap1, b1v.y);
            ffma2(c[2][0], ap2, b0.x); ffma2(c[2][1], ap2, b0.y);
            ffma2(c[2][2], ap2, b1v.x); ffma2(c[2][3], ap2, b1v.y);
            ffma2(c[3][0], ap3, b0.x); ffma2(c[3][1], ap3, b0.y);
            ffma2(c[3][2], ap3, b1v.x); ffma2(c[3][3], ap3, b1v.y);
        }
        __syncthreads();
    }

#pragma unroll
    for (int i = 0; i < 4; i++) {
        int m = m0 + ty * 4 + i;
        if (m >= cnt) break;
        float* zrow = g_zbuf + (size_t)(seg + m) * DOUT;
#pragma unroll
        for (int j = 0; j < 4; j++) {
            int col = n0 + ((j >> 1) ? 64 : 0) + tx * 4 + (j & 1) * 2;
            float2 p = unpack2(c[i][j]);
            zrow[col + 0] = p.x + b2[e * DOUT + col + 0];
            zrow[col + 1] = p.y + b2[e * DOUT + col + 1];
        }
    }
}

// ---------------- kernel 6: softmax of 2 expert rows + combine + log ---------
// y[b, :] = log( g0*softmax(z_s0)[:] + g1*softmax(z_s1)[:] ), EPS clamp
__global__ __launch_bounds__(256) void combine_kernel(float* __restrict__ out, int B) {
    const int b = blockIdx.x;
    const int tid = threadIdx.x;
    const int lane = tid & 31, wid = tid >> 5;

    const int s0 = g_assign_slot[2 * b + 0];
    const int s1 = g_assign_slot[2 * b + 1];
    const float g0 = g_tok_g[2 * b + 0];
    const float g1 = g_tok_g[2 * b + 1];
    const float* z0 = g_zbuf + (size_t)s0 * DOUT;
    const float* z1 = g_zbuf + (size_t)s1 * DOUT;

    float v0[3], v1[3];
#pragma unroll
    for (int r = 0; r < 3; r++) {
        v0[r] = z0[tid + r * 256];
        v1[r] = z1[tid + r * 256];
    }

    __shared__ float red[4][8];

    // block max for each expert row
    float m0 = fmaxf(fmaxf(v0[0], v0[1]), v0[2]);
    float m1 = fmaxf(fmaxf(v1[0], v1[1]), v1[2]);
#pragma unroll
    for (int off = 16; off; off >>= 1) {
        m0 = fmaxf(m0, __shfl_xor_sync(0xffffffffu, m0, off));
        m1 = fmaxf(m1, __shfl_xor_sync(0xffffffffu, m1, off));
    }
    if (lane == 0) { red[0][wid] = m0; red[1][wid] = m1; }
    __syncthreads();
    m0 = red[0][0]; m1 = red[1][0];
#pragma unroll
    for (int w = 1; w < 8; w++) {
        m0 = fmaxf(m0, red[0][w]);
        m1 = fmaxf(m1, red[1][w]);
    }

    // block sum of exp for each expert row
    float e0[3], e1[3];
    float s0sum = 0.0f, s1sum = 0.0f;
#pragma unroll
    for (int r = 0; r < 3; r++) {
        e0[r] = expf(v0[r] - m0); s0sum += e0[r];
        e1[r] = expf(v1[r] - m1); s1sum += e1[r];
    }
#pragma unroll
    for (int off = 16; off; off >>= 1) {
        s0sum += __shfl_xor_sync(0xffffffffu, s0sum, off);
        s1sum += __shfl_xor_sync(0xffffffffu, s1sum, off);
    }
    __syncthreads();  // red reuse
    if (lane == 0) { red[2][wid] = s0sum; red[3][wid] = s1sum; }
    __syncthreads();
    s0sum = 0.0f; s1sum = 0.0f;
#pragma unroll
    for (int w = 0; w < 8; w++) { s0sum += red[2][w]; s1sum += red[3][w]; }

    const float is0 = g0 / s0sum;
    const float is1 = g1 / s1sum;
#pragma unroll
    for (int r = 0; r < 3; r++) {
        int c = tid + r * 256;
        float comb = is0 * e0[r] + is1 * e1[r];
        if (comb == 0.0f) comb = 2.220446049250313e-16f;  // np.finfo(float64).eps
        out[(size_t)b * DOUT + c] = logf(comb);
    }
}

// ---------------- launch -----------------------------------------------------
extern "C" void kernel_launch(void* const* d_in, const int* in_sizes, int n_in,
                              void* d_out, int out_size) {
    const float* x  = (const float*)d_in[0];
    const float* wg = (const float*)d_in[1];
    const float* W1 = (const float*)d_in[2];
    const float* b1 = (const float*)d_in[3];
    const float* W2 = (const float*)d_in[4];
    const float* b2 = (const float*)d_in[5];
    float* out = (float*)d_out;
    const int B = in_sizes[0] / DIN;

    init_kernel<<<1, 32>>>();
    gating_kernel<<<(B * 32 + 255) / 256, 256>>>(x, wg, B);
    prefix_loss_kernel<<<1, 32>>>(out, B, out_size);
    scatter_kernel<<<(B + 255) / 256, 256>>>(B);

    dim3 grid1(DH / 128, (B + 63) / 64, NEXP);
    gemm1_kernel<<<grid1, 256>>>(x, W1, b1);
    dim3 grid2(DOUT / 128, (B + 63) / 64, NEXP);
    gemm2_kernel<<<grid2, 256>>>(W2, b2);

    combine_kernel<<<B, 256>>>(out, B);
}

// round 8
// speedup vs baseline: 2.2341x; 2.2341x over previous
#include <cuda_runtime.h>
#include <cuda_bf16.h>
#include <math.h>
#include <stdint.h>

// Problem constants (shapes fixed by setup_inputs; B derived at launch)
#define MAXB 4096
#define NEXP 8
#define DIN 768
#define DH 2048
#define DOUT 768
#define KSEL 2
#define RPAD 128   // row padding for M-tile overreach past last expert

// ---------------- scratch (device globals; no allocation allowed) ------------
__device__ int   g_counts[NEXP];
__device__ int   g_offsets[NEXP];
__device__ int   g_cursor[NEXP];
__device__ float g_importance[NEXP];
__device__ int   g_tok_e[MAXB * KSEL];
__device__ float g_tok_g[MAXB * KSEL];
__device__ int   g_assign_tok[MAXB * KSEL];
__device__ int   g_assign_slot[MAXB * KSEL];

// split-bf16 operands (hi/lo), gathered/compacted row order. 16B-aligned for
// cp.async / vector access (explicit: do not rely on linker over-alignment).
__device__ __align__(256) __nv_bfloat16 g_xg_hi[(size_t)(MAXB * KSEL + RPAD) * DIN];
__device__ __align__(256) __nv_bfloat16 g_xg_lo[(size_t)(MAXB * KSEL + RPAD) * DIN];
__device__ __align__(256) __nv_bfloat16 g_h_hi [(size_t)(MAXB * KSEL + RPAD) * DH];
__device__ __align__(256) __nv_bfloat16 g_h_lo [(size_t)(MAXB * KSEL + RPAD) * DH];
// transposed + split weights: W1t [E][DH][DIN], W2t [E][DOUT][DH]
__device__ __align__(256) __nv_bfloat16 g_w1t_hi[(size_t)NEXP * DH * DIN];
__device__ __align__(256) __nv_bfloat16 g_w1t_lo[(size_t)NEXP * DH * DIN];
__device__ __align__(256) __nv_bfloat16 g_w2t_hi[(size_t)NEXP * DOUT * DH];
__device__ __align__(256) __nv_bfloat16 g_w2t_lo[(size_t)NEXP * DOUT * DH];
__device__ __align__(256) float g_zbuf[(size_t)MAXB * KSEL * DOUT];

// ---------------- sm_80-era primitives (plain-target-safe) -------------------
__device__ __forceinline__ uint32_t smem_to_u32(const void* p) {
    uint32_t a;
    asm("{ .reg .u64 t; cvta.to.shared.u64 t, %1; cvt.u32.u64 %0, t; }"
        : "=r"(a) : "l"(p));
    return a;
}
__device__ __forceinline__ void cp_async16(uint32_t s, const void* g) {
    asm volatile("cp.async.cg.shared.global [%0], [%1], 16;" :: "r"(s), "l"(g));
}
__device__ __forceinline__ void cp_commit() {
    asm volatile("cp.async.commit_group;" ::: "memory");
}
__device__ __forceinline__ void cp_wait1() {
    asm volatile("cp.async.wait_group 1;" ::: "memory");
}
__device__ __forceinline__ void cp_wait0() {
    asm volatile("cp.async.wait_group 0;" ::: "memory");
}
__device__ __forceinline__ void ldsm4(uint32_t a, uint32_t* r) {
    asm volatile("ldmatrix.sync.aligned.m8n8.x4.shared.b16 {%0,%1,%2,%3}, [%4];"
        : "=r"(r[0]), "=r"(r[1]), "=r"(r[2]), "=r"(r[3]) : "r"(a));
}
__device__ __forceinline__ void ldsm2(uint32_t a, uint32_t* r) {
    asm volatile("ldmatrix.sync.aligned.m8n8.x2.shared.b16 {%0,%1}, [%2];"
        : "=r"(r[0]), "=r"(r[1]) : "r"(a));
}
__device__ __forceinline__ void mma_bf16(float* d, const uint32_t* a, const uint32_t* b) {
    asm volatile(
        "mma.sync.aligned.m16n8k16.row.col.f32.bf16.bf16.f32 "
        "{%0,%1,%2,%3}, {%4,%5,%6,%7}, {%8,%9}, {%0,%1,%2,%3};"
        : "+f"(d[0]), "+f"(d[1]), "+f"(d[2]), "+f"(d[3])
        : "r"(a[0]), "r"(a[1]), "r"(a[2]), "r"(a[3]), "r"(b[0]), "r"(b[1]));
}

__device__ __forceinline__ float gelu_tanh(float v) {
    float v3 = v * v * v;
    return 0.5f * v * (1.0f + tanhf(0.7978845608028654f * (v + 0.044715f * v3)));
}

// ---------------- kernel 0: zero per-launch state ----------------------------
__global__ void init_kernel() {
    int t = threadIdx.x;
    if (t < NEXP) { g_counts[t] = 0; g_importance[t] = 0.0f; }
}

// ---------------- kernel 1: gating (one warp per token) ----------------------
__global__ void gating_kernel(const float* __restrict__ x,
                              const float* __restrict__ wg, int B) {
    __shared__ float sW[NEXP][DIN];
    for (int i = threadIdx.x; i < NEXP * DIN; i += blockDim.x) {
        int e = i / DIN, c = i % DIN;
        sW[e][c] = wg[c * NEXP + e];
    }
    __syncthreads();

    int warp = (blockIdx.x * blockDim.x + threadIdx.x) >> 5;
    int lane = threadIdx.x & 31;
    if (warp >= B) return;

    const float* xr = x + (size_t)warp * DIN;
    float acc[NEXP];
#pragma unroll
    for (int e = 0; e < NEXP; e++) acc[e] = 0.0f;
    for (int i = lane; i < DIN; i += 32) {
        float xv = xr[i];
#pragma unroll
        for (int e = 0; e < NEXP; e++) acc[e] += xv * sW[e][i];
    }
#pragma unroll
    for (int off = 16; off; off >>= 1) {
#pragma unroll
        for (int e = 0; e < NEXP; e++)
            acc[e] += __shfl_down_sync(0xffffffffu, acc[e], off);
    }
    if (lane == 0) {
        int i1 = 0; float v1 = acc[0];
#pragma unroll
        for (int e = 1; e < NEXP; e++) if (acc[e] > v1) { v1 = acc[e]; i1 = e; }
        int i2 = -1; float v2 = -INFINITY;
#pragma unroll
        for (int e = 0; e < NEXP; e++)
            if (e != i1 && acc[e] > v2) { v2 = acc[e]; i2 = e; }
        float e2 = expf(v2 - v1);
        float inv = 1.0f / (1.0f + e2);
        float gA = inv, gB = e2 * inv;
        g_tok_e[2 * warp + 0] = i1;  g_tok_e[2 * warp + 1] = i2;
        g_tok_g[2 * warp + 0] = gA;  g_tok_g[2 * warp + 1] = gB;
        atomicAdd(&g_counts[i1], 1); atomicAdd(&g_counts[i2], 1);
        atomicAdd(&g_importance[i1], gA); atomicAdd(&g_importance[i2], gB);
    }
}

// ---------------- kernel 2: prefix sums + aux loss ---------------------------
__global__ void prefix_loss_kernel(float* __restrict__ d_out, int B, int out_size) {
    if (threadIdx.x == 0 && blockIdx.x == 0) {
        int off = 0;
        for (int e = 0; e < NEXP; e++) {
            g_offsets[e] = off; g_cursor[e] = off; off += g_counts[e];
        }
        float mi = 0.0f, ml = 0.0f;
        for (int e = 0; e < NEXP; e++) { mi += g_importance[e]; ml += (float)g_counts[e]; }
        mi /= NEXP; ml /= NEXP;
        float vi = 0.0f, vl = 0.0f;
        for (int e = 0; e < NEXP; e++) {
            float d1 = g_importance[e] - mi; vi += d1 * d1;
            float d2 = (float)g_counts[e] - ml; vl += d2 * d2;
        }
        vi /= (NEXP - 1); vl /= (NEXP - 1);
        float loss = 0.01f * (vi / (mi * mi + 1e-10f) + vl / (ml * ml + 1e-10f));
        if (out_size > B * DOUT) d_out[(size_t)B * DOUT] = loss;
    }
}

// ---------------- kernel 3: scatter ------------------------------------------
__global__ void scatter_kernel(int B) {
    int b = blockIdx.x * blockDim.x + threadIdx.x;
    if (b >= B) return;
#pragma unroll
    for (int j = 0; j < KSEL; j++) {
        int e = g_tok_e[2 * b + j];
        int slot = atomicAdd(&g_cursor[e], 1);
        g_assign_tok[slot] = b;
        g_assign_slot[2 * b + j] = slot;
    }
}

// ---------------- kernel 3b: gather x rows + bf16 split ----------------------
__global__ void gather_split_x(const float* __restrict__ x) {
    int s = blockIdx.x;
    int tok = g_assign_tok[s];
    const float* xr = x + (size_t)tok * DIN;
    size_t ob = (size_t)s * DIN;
    for (int c = threadIdx.x; c < DIN; c += blockDim.x) {
        float v = xr[c];
        __nv_bfloat16 hi = __float2bfloat16(v);
        __nv_bfloat16 lo = __float2bfloat16(v - __bfloat162float(hi));
        g_xg_hi[ob + c] = hi;
        g_xg_lo[ob + c] = lo;
    }
}

// ---------------- kernel 3c: weight transpose + bf16 split -------------------
// in: [E][R][C] fp32 -> out_hi/lo: [E][C][R] bf16
__global__ void transpose_split_kernel(const float* __restrict__ in,
                                       __nv_bfloat16* __restrict__ ohi,
                                       __nv_bfloat16* __restrict__ olo,
                                       int R, int C) {
    __shared__ float t[32][33];
    int e = blockIdx.z;
    const float* src = in + (size_t)e * R * C;
    int c0 = blockIdx.x * 32, r0 = blockIdx.y * 32;
    int tx = threadIdx.x, ty = threadIdx.y;
#pragma unroll
    for (int i = 0; i < 4; i++)
        t[ty + 8 * i][tx] = src[(size_t)(r0 + ty + 8 * i) * C + c0 + tx];
    __syncthreads();
    size_t ob = (size_t)e * C * R;
#pragma unroll
    for (int i = 0; i < 4; i++) {
        float v = t[tx][ty + 8 * i];
        int oc = c0 + ty + 8 * i, orr = r0 + tx;
        __nv_bfloat16 hi = __float2bfloat16(v);
        __nv_bfloat16 lo = __float2bfloat16(v - __bfloat162float(hi));
        ohi[ob + (size_t)oc * R + orr] = hi;
        olo[ob + (size_t)oc * R + orr] = lo;
    }
}

// ============================================================================
// mma.sync grouped GEMM: CTA tile 128x128, k-tile 32, 8 warps (2 M x 4 N),
// warp tile 64x32, m16n8k16 bf16 with 3xBF16 split into fp32 accumulators.
// smem rows: 32 halves = 64B data + 16B pad -> 80B pitch (LDSM conflict-free:
// row strides mod 32 words = {0,20,8,28,16,4,24,12}).
// Stage = {Ahi, Alo, Bhi, Blo} 128 rows each = 40960 B; 2 stages, cp.async.
// ============================================================================
#define PITCH 80
#define MATBYTES (128 * PITCH)          // 10240
#define STAGE_BYTES (4 * MATBYTES)      // 40960
#define GEMM_SMEM (2 * STAGE_BYTES)     // 81920

__device__ __forceinline__ void stage_copy(uint32_t sbase,
        const __nv_bfloat16* __restrict__ gah, const __nv_bfloat16* __restrict__ gal,
        const __nv_bfloat16* __restrict__ gbh, const __nv_bfloat16* __restrict__ gbl,
        int ktot, int k0, int tid)
{
    // each thread: rows (tid>>2) and (tid>>2)+64, 16B chunk (tid&3), x4 matrices
    const int row = tid >> 2, c = tid & 3;
    const uint32_t so = sbase + row * PITCH + c * 16;
    const size_t go  = (size_t)row * ktot + k0 + c * 8;
    const size_t go2 = go + (size_t)64 * ktot;
    const uint32_t so2 = so + 64 * PITCH;
    cp_async16(so,                  gah + go);
    cp_async16(so2,                 gah + go2);
    cp_async16(so + MATBYTES,       gal + go);
    cp_async16(so2 + MATBYTES,      gal + go2);
    cp_async16(so + 2 * MATBYTES,   gbh + go);
    cp_async16(so2 + 2 * MATBYTES,  gbh + go2);
    cp_async16(so + 3 * MATBYTES,   gbl + go);
    cp_async16(so2 + 3 * MATBYTES,  gbl + go2);
}

template<int KTOT, int NTOT, bool GELU>
__global__ __launch_bounds__(256) void gemm_mma_kernel(
    const __nv_bfloat16* __restrict__ Ahi, const __nv_bfloat16* __restrict__ Alo,
    const __nv_bfloat16* __restrict__ Bhi, const __nv_bfloat16* __restrict__ Blo,
    const float* __restrict__ bias,
    __nv_bfloat16* __restrict__ out_hi, __nv_bfloat16* __restrict__ out_lo,
    float* __restrict__ out_f)
{
    const int e = blockIdx.z;
    const int cnt = g_counts[e];
    const int m0 = blockIdx.y * 128;
    if (m0 >= cnt) return;
    const int n0 = blockIdx.x * 128;
    const int seg = g_offsets[e];

    extern __shared__ char smem[];
    const uint32_t sb = smem_to_u32(smem);
    const int tid = threadIdx.x, wid = tid >> 5, lane = tid & 31;
    const int wm = wid & 1, wn = wid >> 1;

    const __nv_bfloat16* gah = Ahi + (size_t)(seg + m0) * KTOT;
    const __nv_bfloat16* gal = Alo + (size_t)(seg + m0) * KTOT;
    const __nv_bfloat16* gbh = Bhi + (size_t)e * NTOT * KTOT + (size_t)n0 * KTOT;
    const __nv_bfloat16* gbl = Blo + (size_t)e * NTOT * KTOT + (size_t)n0 * KTOT;

    constexpr int NK = KTOT / 32;

    float acc[4][4][4];
#pragma unroll
    for (int i = 0; i < 4; i++)
#pragma unroll
        for (int j = 0; j < 4; j++)
#pragma unroll
            for (int k = 0; k < 4; k++) acc[i][j][k] = 0.0f;

    // ldmatrix lane address offsets (within a stage's matrix)
    const uint32_t aoff = (uint32_t)((wm * 64 + (lane & 15)) * PITCH + (lane >> 4) * 16);
    const uint32_t boff = (uint32_t)((wn * 32 + (lane & 7)) * PITCH + ((lane >> 3) & 1) * 16);

    stage_copy(sb, gah, gal, gbh, gbl, KTOT, 0, tid);
    cp_commit();

    for (int t = 0; t < NK; t++) {
        if (t + 1 < NK) {
            stage_copy(sb + ((t + 1) & 1) * STAGE_BYTES,
                       gah, gal, gbh, gbl, KTOT, (t + 1) * 32, tid);
            cp_commit();
            cp_wait1();
        } else {
            cp_wait0();
        }
        __syncthreads();

        const uint32_t st = sb + (t & 1) * STAGE_BYTES;
#pragma unroll
        for (int ks = 0; ks < 2; ks++) {
            uint32_t ah[4][4], al[4][4], bh[4][2], bl[4][2];
#pragma unroll
            for (int mt = 0; mt < 4; mt++) {
                uint32_t a = st + aoff + mt * (16 * PITCH) + ks * 32;
                ldsm4(a, ah[mt]);
                ldsm4(a + MATBYTES, al[mt]);
            }
#pragma unroll
            for (int nt = 0; nt < 4; nt++) {
                uint32_t b = st + 2 * MATBYTES + boff + nt * (8 * PITCH) + ks * 32;
                ldsm2(b, bh[nt]);
                ldsm2(b + MATBYTES, bl[nt]);
            }
#pragma unroll
            for (int mt = 0; mt < 4; mt++)
#pragma unroll
                for (int nt = 0; nt < 4; nt++) {
                    mma_bf16(acc[mt][nt], ah[mt], bh[nt]);
                    mma_bf16(acc[mt][nt], ah[mt], bl[nt]);
                    mma_bf16(acc[mt][nt], al[mt], bh[nt]);
                }
        }
        __syncthreads();
    }

    // epilogue: acc[mt][nt] = rows r0, r0+8; cols cc, cc+1
#pragma unroll
    for (int mt = 0; mt < 4; mt++) {
        const int r0 = m0 + wm * 64 + mt * 16 + (lane >> 2);
#pragma unroll
        for (int nt = 0; nt < 4; nt++) {
            const int cc = n0 + wn * 32 + nt * 8 + (lane & 3) * 2;
            const float bb0 = bias[(size_t)e * NTOT + cc];
            const float bb1 = bias[(size_t)e * NTOT + cc + 1];
#pragma unroll
            for (int hh = 0; hh < 2; hh++) {
                const int r = r0 + hh * 8;
                if (r < cnt) {
                    float v0 = acc[mt][nt][hh * 2 + 0] + bb0;
                    float v1 = acc[mt][nt][hh * 2 + 1] + bb1;
                    size_t orow = (size_t)(seg + r) * NTOT + cc;
                    if (GELU) {
                        float h0 = gelu_tanh(v0), h1 = gelu_tanh(v1);
                        __nv_bfloat16 h0h = __float2bfloat16(h0);
                        __nv_bfloat16 h1h = __float2bfloat16(h1);
                        __nv_bfloat162 hi2, lo2;
                        hi2.x = h0h; hi2.y = h1h;
                        lo2.x = __float2bfloat16(h0 - __bfloat162float(h0h));
                        lo2.y = __float2bfloat16(h1 - __bfloat162float(h1h));
                        *reinterpret_cast<__nv_bfloat162*>(out_hi + orow) = hi2;
                        *reinterpret_cast<__nv_bfloat162*>(out_lo + orow) = lo2;
                    } else {
                        float2 z; z.x = v0; z.y = v1;
                        *reinterpret_cast<float2*>(out_f + orow) = z;
                    }
                }
            }
        }
    }
}

// ---------------- kernel 6: softmax of 2 expert rows + combine + log ---------
__global__ __launch_bounds__(256) void combine_kernel(float* __restrict__ out, int B) {
    const int b = blockIdx.x;
    const int tid = threadIdx.x;
    const int lane = tid & 31, wid = tid >> 5;

    const int s0 = g_assign_slot[2 * b + 0];
    const int s1 = g_assign_slot[2 * b + 1];
    const float g0 = g_tok_g[2 * b + 0];
    const float g1 = g_tok_g[2 * b + 1];
    const float* z0 = g_zbuf + (size_t)s0 * DOUT;
    const float* z1 = g_zbuf + (size_t)s1 * DOUT;

    float v0[3], v1[3];
#pragma unroll
    for (int r = 0; r < 3; r++) { v0[r] = z0[tid + r * 256]; v1[r] = z1[tid + r * 256]; }

    __shared__ float red[4][8];
    float m0 = fmaxf(fmaxf(v0[0], v0[1]), v0[2]);
    float m1 = fmaxf(fmaxf(v1[0], v1[1]), v1[2]);
#pragma unroll
    for (int off = 16; off; off >>= 1) {
        m0 = fmaxf(m0, __shfl_xor_sync(0xffffffffu, m0, off));
        m1 = fmaxf(m1, __shfl_xor_sync(0xffffffffu, m1, off));
    }
    if (lane == 0) { red[0][wid] = m0; red[1][wid] = m1; }
    __syncthreads();
    m0 = red[0][0]; m1 = red[1][0];
#pragma unroll
    for (int w = 1; w < 8; w++) {
        m0 = fmaxf(m0, red[0][w]);
        m1 = fmaxf(m1, red[1][w]);
    }
    float e0[3], e1[3], s0s = 0.0f, s1s = 0.0f;
#pragma unroll
    for (int r = 0; r < 3; r++) {
        e0[r] = expf(v0[r] - m0); s0s += e0[r];
        e1[r] = expf(v1[r] - m1); s1s += e1[r];
    }
#pragma unroll
    for (int off = 16; off; off >>= 1) {
        s0s += __shfl_xor_sync(0xffffffffu, s0s, off);
        s1s += __shfl_xor_sync(0xffffffffu, s1s, off);
    }
    __syncthreads();
    if (lane == 0) { red[2][wid] = s0s; red[3][wid] = s1s; }
    __syncthreads();
    s0s = 0.0f; s1s = 0.0f;
#pragma unroll
    for (int w = 0; w < 8; w++) { s0s += red[2][w]; s1s += red[3][w]; }

    const float is0 = g0 / s0s;
    const float is1 = g1 / s1s;
#pragma unroll
    for (int r = 0; r < 3; r++) {
        int c = tid + r * 256;
        float comb = is0 * e0[r] + is1 * e1[r];
        if (comb == 0.0f) comb = 2.220446049250313e-16f;  // np.finfo(float64).eps
        out[(size_t)b * DOUT + c] = logf(comb);
    }
}

// ---------------- launch -----------------------------------------------------
extern "C" void kernel_launch(void* const* d_in, const int* in_sizes, int n_in,
                              void* d_out, int out_size) {
    const float* x  = (const float*)d_in[0];
    const float* wg = (const float*)d_in[1];
    const float* W1 = (const float*)d_in[2];
    const float* b1 = (const float*)d_in[3];
    const float* W2 = (const float*)d_in[4];
    const float* b2 = (const float*)d_in[5];
    float* out = (float*)d_out;
    const int B = in_sizes[0] / DIN;
    const int R = B * KSEL;  // total assignments (exactly 2 per token)

    // resolve device-global pointers (host-side query, capture-safe)
    __nv_bfloat16 *xg_hi, *xg_lo, *h_hi, *h_lo, *w1h, *w1l, *w2h, *w2l;
    float* zb;
    cudaGetSymbolAddress((void**)&xg_hi, g_xg_hi);
    cudaGetSymbolAddress((void**)&xg_lo, g_xg_lo);
    cudaGetSymbolAddress((void**)&h_hi,  g_h_hi);
    cudaGetSymbolAddress((void**)&h_lo,  g_h_lo);
    cudaGetSymbolAddress((void**)&w1h,   g_w1t_hi);
    cudaGetSymbolAddress((void**)&w1l,   g_w1t_lo);
    cudaGetSymbolAddress((void**)&w2h,   g_w2t_hi);
    cudaGetSymbolAddress((void**)&w2l,   g_w2t_lo);
    cudaGetSymbolAddress((void**)&zb,    g_zbuf);

    cudaFuncSetAttribute(gemm_mma_kernel<DIN, DH, true>,
                         cudaFuncAttributeMaxDynamicSharedMemorySize, GEMM_SMEM);
    cudaFuncSetAttribute(gemm_mma_kernel<DH, DOUT, false>,
                         cudaFuncAttributeMaxDynamicSharedMemorySize, GEMM_SMEM);

    init_kernel<<<1, 32>>>();
    gating_kernel<<<(B * 32 + 255) / 256, 256>>>(x, wg, B);
    prefix_loss_kernel<<<1, 32>>>(out, B, out_size);
    scatter_kernel<<<(B + 255) / 256, 256>>>(B);
    gather_split_x<<<R, 256>>>(x);

    // W1 [E][DIN][DH] -> W1t [E][DH][DIN]; W2 [E][DH][DOUT] -> W2t [E][DOUT][DH]
    transpose_split_kernel<<<dim3(DH / 32, DIN / 32, NEXP), dim3(32, 8)>>>(
        W1, w1h, w1l, DIN, DH);
    transpose_split_kernel<<<dim3(DOUT / 32, DH / 32, NEXP), dim3(32, 8)>>>(
        W2, w2h, w2l, DH, DOUT);

    const int mt = (R + 127) / 128;  // worst-case per-expert M tiles
    gemm_mma_kernel<DIN, DH, true><<<dim3(DH / 128, mt, NEXP), 256, GEMM_SMEM>>>(
        xg_hi, xg_lo, w1h, w1l, b1, h_hi, h_lo, nullptr);
    gemm_mma_kernel<DH, DOUT, false><<<dim3(DOUT / 128, mt, NEXP), 256, GEMM_SMEM>>>(
        h_hi, h_lo, w2h, w2l, b2, nullptr, nullptr, zb);

    combine_kernel<<<B, 256>>>(out, B);
}